// round 1
// baseline (speedup 1.0000x reference)
#include <cuda_runtime.h>
#include <cuda_bf16.h>
#include <cstdint>

#define NP 100000
#define NA 50000
#define EPP 1600000
#define EAP 800000
#define EPA 800000

// ---------------- scratch (device globals; reused across sequential convs) ----
__device__ __align__(16) float g_hs[NP * 128];     // transformed src features (largest case)
__device__ __align__(16) float g_es[NP * 4];       // per-src attn logits
__device__ __align__(16) float g_ed[NP * 4];       // per-dst attn logits
__device__ __align__(16) float g_m[NP * 4];        // segment max
__device__ __align__(16) float g_den[NP * 4];      // segment expsum
__device__ __align__(16) float g_accp[NP * 128];   // layer1 paper accum -> h1_paper (in place)
__device__ __align__(16) float g_acca[NA * 128];   // layer1 author accum -> h1_author
__device__ __align__(16) float g_vd1[3 * 128 * 4]; // Wdst1 . adst1 folded
__device__ __align__(16) float g_vd2[3 * 128 * 4];

// ---------------- helpers ----------------------------------------------------
__device__ __forceinline__ float lrelu(float x) { return x > 0.f ? x : 0.2f * x; }

__device__ __forceinline__ void atomicMaxF(float* addr, float v) {
    if ((__float_as_uint(v) >> 31) == 0)
        atomicMax((int*)addr, __float_as_int(v));          // v >= +0
    else
        atomicMin((unsigned int*)addr, __float_as_uint(v)); // v < 0 (incl -0)
}

__device__ __forceinline__ void redAdd4(float* p, float4 v) {
    asm volatile("red.global.add.v4.f32 [%0], {%1,%2,%3,%4};"
                 :: "l"(p), "f"(v.x), "f"(v.y), "f"(v.z), "f"(v.w) : "memory");
}

// ---------------- generic fill -----------------------------------------------
__global__ void fill_kernel(float* __restrict__ p, float v, int n) {
    int i = blockIdx.x * blockDim.x + threadIdx.x;
    if (i < n) p[i] = v;
}

// ---------------- SGEMM: C[M,N] = A[M,128] @ B[128,N]  (N multiple of 64) -----
__global__ void sgemm(const float* __restrict__ A, const float* __restrict__ B,
                      float* __restrict__ C, int M, int N) {
    const int K = 128;
    __shared__ float As[16][68];
    __shared__ float Bs[16][64];
    int tid = threadIdx.x;
    int m0 = blockIdx.y * 64, n0 = blockIdx.x * 64;
    int aRow = tid >> 2, aCol = (tid & 3) << 2;
    int bRow = tid >> 4, bCol = (tid & 15) << 2;
    int tx = tid & 15, ty = tid >> 4;
    float acc[4][4] = {};
    for (int k0 = 0; k0 < K; k0 += 16) {
        float4 av = make_float4(0.f, 0.f, 0.f, 0.f);
        if (m0 + aRow < M)
            av = *(const float4*)(A + (size_t)(m0 + aRow) * K + k0 + aCol);
        As[aCol + 0][aRow] = av.x;
        As[aCol + 1][aRow] = av.y;
        As[aCol + 2][aRow] = av.z;
        As[aCol + 3][aRow] = av.w;
        *(float4*)&Bs[bRow][bCol] =
            *(const float4*)(B + (size_t)(k0 + bRow) * N + n0 + bCol);
        __syncthreads();
#pragma unroll
        for (int k = 0; k < 16; k++) {
            float a[4], b[4];
#pragma unroll
            for (int i = 0; i < 4; i++) a[i] = As[k][ty * 4 + i];
#pragma unroll
            for (int j = 0; j < 4; j++) b[j] = Bs[k][tx * 4 + j];
#pragma unroll
            for (int i = 0; i < 4; i++)
#pragma unroll
                for (int j = 0; j < 4; j++) acc[i][j] += a[i] * b[j];
        }
        __syncthreads();
    }
#pragma unroll
    for (int i = 0; i < 4; i++) {
        int m = m0 + ty * 4 + i;
        if (m < M) {
            float4 o = make_float4(acc[i][0], acc[i][1], acc[i][2], acc[i][3]);
            *(float4*)(C + (size_t)m * N + n0 + tx * 4) = o;
        }
    }
}

// ---------------- vd[r][f][h] = sum_c Wd[r][f][h*C+c] * ad[r][h][c] -----------
__global__ void compute_vd(const float* __restrict__ Wd, const float* __restrict__ ad,
                           float* __restrict__ vd, int D, int C) {
    int i = blockIdx.x * blockDim.x + threadIdx.x;
    if (i >= 3 * 128 * 4) return;
    int h = i & 3;
    int f = (i >> 2) & 127;
    int r = i >> 9;
    const float* W = Wd + (size_t)r * 128 * D + (size_t)f * D + h * C;
    const float* a = ad + r * 4 * C + h * C;
    float s = 0.f;
    for (int c = 0; c < C; c++) s += W[c] * a[c];
    vd[r * 512 + f * 4 + h] = s;
}

// ---------------- es[n,h] = sum_c hs[n,h*C+c] * a[h*C+c] ----------------------
__global__ void es_reduce(const float* __restrict__ hs, const float* __restrict__ a,
                          float* __restrict__ es, int N, int D, int C) {
    int gid = blockIdx.x * blockDim.x + threadIdx.x;
    int G = D >> 2;                 // lanes per node (32 or 16)
    int g = gid / G;
    int l = gid % G;
    bool valid = g < N;
    if (!valid) g = 0;
    float4 h4 = ((const float4*)hs)[(size_t)g * G + l];
    float4 a4 = ((const float4*)a)[l];
    float p = h4.x * a4.x + h4.y * a4.y + h4.z * a4.z + h4.w * a4.w;
    int red = C >> 2;               // lanes per head (8 or 4)
    for (int off = red >> 1; off; off >>= 1)
        p += __shfl_down_sync(0xffffffffu, p, off, red);
    if (valid && (l % red) == 0) es[g * 4 + l / red] = p;
}

// ---------------- ed[n,:] = x[n,:] @ vd[128,4]  (warp per node) ---------------
__global__ void ed_matvec(const float* __restrict__ x, const float* __restrict__ vd,
                          float* __restrict__ ed, int N) {
    int warp = (blockIdx.x * blockDim.x + threadIdx.x) >> 5;
    int lane = threadIdx.x & 31;
    if (warp >= N) return;
    float4 x4 = ((const float4*)x)[(size_t)warp * 32 + lane];
    const float4* v4 = (const float4*)vd;
    float4 a0 = v4[4 * lane + 0], a1 = v4[4 * lane + 1];
    float4 a2 = v4[4 * lane + 2], a3 = v4[4 * lane + 3];
    float4 acc;
    acc.x = x4.x * a0.x + x4.y * a1.x + x4.z * a2.x + x4.w * a3.x;
    acc.y = x4.x * a0.y + x4.y * a1.y + x4.z * a2.y + x4.w * a3.y;
    acc.z = x4.x * a0.z + x4.y * a1.z + x4.z * a2.z + x4.w * a3.z;
    acc.w = x4.x * a0.w + x4.y * a1.w + x4.z * a2.w + x4.w * a3.w;
    for (int off = 16; off; off >>= 1) {
        acc.x += __shfl_down_sync(0xffffffffu, acc.x, off);
        acc.y += __shfl_down_sync(0xffffffffu, acc.y, off);
        acc.z += __shfl_down_sync(0xffffffffu, acc.z, off);
        acc.w += __shfl_down_sync(0xffffffffu, acc.w, off);
    }
    if (lane == 0) ((float4*)ed)[warp] = acc;
}

// ---------------- edge pass A: segment max -----------------------------------
__global__ void edge_max(const int* __restrict__ src, const int* __restrict__ dst,
                         const float* __restrict__ es, const float* __restrict__ ed,
                         float* __restrict__ m, int E) {
    int i = blockIdx.x * blockDim.x + threadIdx.x;
    if (i >= E) return;
    int s = src[i], d = dst[i];
    float4 a = ((const float4*)es)[s];
    float4 b = ((const float4*)ed)[d];
    atomicMaxF(&m[d * 4 + 0], lrelu(a.x + b.x));
    atomicMaxF(&m[d * 4 + 1], lrelu(a.y + b.y));
    atomicMaxF(&m[d * 4 + 2], lrelu(a.z + b.z));
    atomicMaxF(&m[d * 4 + 3], lrelu(a.w + b.w));
}

// ---------------- edge pass B: segment expsum --------------------------------
__global__ void edge_expsum(const int* __restrict__ src, const int* __restrict__ dst,
                            const float* __restrict__ es, const float* __restrict__ ed,
                            const float* __restrict__ m, float* __restrict__ den, int E) {
    int i = blockIdx.x * blockDim.x + threadIdx.x;
    if (i >= E) return;
    int s = src[i], d = dst[i];
    float4 a = ((const float4*)es)[s];
    float4 b = ((const float4*)ed)[d];
    float4 mx = ((const float4*)m)[d];
    float4 ee;
    ee.x = __expf(lrelu(a.x + b.x) - mx.x);
    ee.y = __expf(lrelu(a.y + b.y) - mx.y);
    ee.z = __expf(lrelu(a.z + b.z) - mx.z);
    ee.w = __expf(lrelu(a.w + b.w) - mx.w);
    redAdd4(den + (size_t)d * 4, ee);
}

// ---------------- edge pass C: scatter alpha * hs[src] -> acc[dst] ------------
template <int D, int C>
__global__ void edge_scatter(const int* __restrict__ src, const int* __restrict__ dst,
                             const float* __restrict__ es, const float* __restrict__ ed,
                             const float* __restrict__ m, const float* __restrict__ den,
                             const float* __restrict__ hs, float* __restrict__ acc, int E) {
    constexpr int G = D / 4;  // lanes per edge (32 or 16)
    int gid = blockIdx.x * blockDim.x + threadIdx.x;
    int e = gid / G;
    bool valid = e < E;
    if (!valid) e = 0;
    int lane = threadIdx.x & 31;
    int lg = lane & (G - 1);
    int s = src[e], d = dst[e];
    float aval = 0.f;
    if (lg < 4) {
        int h = lg;
        float ee = lrelu(es[s * 4 + h] + ed[d * 4 + h]);
        aval = __expf(ee - m[d * 4 + h]) / (den[d * 4 + h] + 1e-16f);
    }
    int head = (lg * 4) / C;
    float alpha = __shfl_sync(0xffffffffu, aval, (lane - lg) + head);
    float4 v = ((const float4*)hs)[(size_t)s * G + lg];
    float4 o = make_float4(v.x * alpha, v.y * alpha, v.z * alpha, v.w * alpha);
    if (valid) redAdd4(acc + (size_t)d * D + lg * 4, o);
}

// ---------------- bias (+ optional relu), in place ----------------------------
__global__ void bias_act(float* __restrict__ acc, const float* __restrict__ b0,
                         const float* __restrict__ b1, int n, int D, int relu) {
    int i = blockIdx.x * blockDim.x + threadIdx.x;
    if (i >= n * D) return;
    int j = i % D;
    float v = acc[i] + b0[j] + (b1 ? b1[j] : 0.f);
    acc[i] = relu ? fmaxf(v, 0.f) : v;
}

// =============================================================================
extern "C" void kernel_launch(void* const* d_in, const int* in_sizes, int n_in,
                              void* d_out, int out_size) {
    const float* x_p = (const float*)d_in[0];
    const float* x_a = (const float*)d_in[1];
    const int* src_pp = (const int*)d_in[2];
    const int* dst_pp = (const int*)d_in[3];
    const int* src_ap = (const int*)d_in[4];
    const int* dst_ap = (const int*)d_in[5];
    const int* src_pa = (const int*)d_in[6];
    const int* dst_pa = (const int*)d_in[7];
    const float* Wsrc1 = (const float*)d_in[8];
    const float* Wdst1 = (const float*)d_in[9];
    const float* asrc1 = (const float*)d_in[10];
    const float* adst1 = (const float*)d_in[11];
    const float* b1 = (const float*)d_in[12];
    const float* Wsrc2 = (const float*)d_in[13];
    const float* Wdst2 = (const float*)d_in[14];
    const float* asrc2 = (const float*)d_in[15];
    const float* adst2 = (const float*)d_in[16];
    const float* b2 = (const float*)d_in[17];
    float* out = (float*)d_out;

    void* p;
    cudaGetSymbolAddress(&p, g_hs);   float* hs   = (float*)p;
    cudaGetSymbolAddress(&p, g_es);   float* es   = (float*)p;
    cudaGetSymbolAddress(&p, g_ed);   float* ed   = (float*)p;
    cudaGetSymbolAddress(&p, g_m);    float* m    = (float*)p;
    cudaGetSymbolAddress(&p, g_den);  float* den  = (float*)p;
    cudaGetSymbolAddress(&p, g_accp); float* accp = (float*)p;
    cudaGetSymbolAddress(&p, g_acca); float* acca = (float*)p;
    cudaGetSymbolAddress(&p, g_vd1);  float* vd1  = (float*)p;
    cudaGetSymbolAddress(&p, g_vd2);  float* vd2  = (float*)p;

    const int TB = 256;
    auto blocks = [](long long n) { return (int)((n + 255) / 256); };

    // fold Wdst . adst  ->  vd
    compute_vd<<<blocks(3 * 128 * 4), TB>>>(Wdst1, adst1, vd1, 128, 32);
    compute_vd<<<blocks(3 * 128 * 4), TB>>>(Wdst2, adst2, vd2, 64, 16);

    auto conv = [&](const float* xs, int Ns, const float* xd, int Nd,
                    const int* src, const int* dst, int E,
                    const float* Ws, const float* a_s, const float* vd,
                    float* acc, int D, int C) {
        dim3 grid(D / 64, (Ns + 63) / 64);
        sgemm<<<grid, 256>>>(xs, Ws, hs, Ns, D);
        int G = D / 4;
        es_reduce<<<blocks((long long)Ns * G), TB>>>(hs, a_s, es, Ns, D, C);
        ed_matvec<<<blocks((long long)Nd * 32), TB>>>(xd, vd, ed, Nd);
        fill_kernel<<<blocks(Nd * 4), TB>>>(m, -INFINITY, Nd * 4);
        fill_kernel<<<blocks(Nd * 4), TB>>>(den, 0.f, Nd * 4);
        edge_max<<<blocks(E), TB>>>(src, dst, es, ed, m, E);
        edge_expsum<<<blocks(E), TB>>>(src, dst, es, ed, m, den, E);
        if (D == 128)
            edge_scatter<128, 32><<<blocks((long long)E * 32), TB>>>(src, dst, es, ed, m, den, hs, acc, E);
        else
            edge_scatter<64, 16><<<blocks((long long)E * 16), TB>>>(src, dst, es, ed, m, den, hs, acc, E);
    };

    // ---------------- layer 1 (D=128, C=32) ----------------
    fill_kernel<<<blocks((long long)NP * 128), TB>>>(accp, 0.f, NP * 128);
    fill_kernel<<<blocks((long long)NA * 128), TB>>>(acca, 0.f, NA * 128);

    conv(x_p, NP, x_p, NP, src_pp, dst_pp, EPP,
         Wsrc1 + 0 * 128 * 128, asrc1 + 0 * 128, vd1 + 0 * 512, accp, 128, 32);
    conv(x_a, NA, x_p, NP, src_ap, dst_ap, EAP,
         Wsrc1 + 1 * 128 * 128, asrc1 + 1 * 128, vd1 + 1 * 512, accp, 128, 32);
    conv(x_p, NP, x_a, NA, src_pa, dst_pa, EPA,
         Wsrc1 + 2 * 128 * 128, asrc1 + 2 * 128, vd1 + 2 * 512, acca, 128, 32);

    bias_act<<<blocks((long long)NP * 128), TB>>>(accp, b1 + 0, b1 + 128, NP, 128, 1);
    bias_act<<<blocks((long long)NA * 128), TB>>>(acca, b1 + 256, (const float*)nullptr, NA, 128, 1);

    // ---------------- layer 2 (D=64, C=16), accumulate straight into d_out ----
    fill_kernel<<<blocks((long long)(NP + NA) * 64), TB>>>(out, 0.f, (NP + NA) * 64);

    conv(accp, NP, accp, NP, src_pp, dst_pp, EPP,
         Wsrc2 + 0 * 128 * 64, asrc2 + 0 * 64, vd2 + 0 * 512, out, 64, 16);
    conv(acca, NA, accp, NP, src_ap, dst_ap, EAP,
         Wsrc2 + 1 * 128 * 64, asrc2 + 1 * 64, vd2 + 1 * 512, out, 64, 16);
    conv(accp, NP, acca, NA, src_pa, dst_pa, EPA,
         Wsrc2 + 2 * 128 * 64, asrc2 + 2 * 64, vd2 + 2 * 512, out + (size_t)NP * 64, 64, 16);

    bias_act<<<blocks((long long)NP * 64), TB>>>(out, b2 + 0, b2 + 64, NP, 64, 0);
    bias_act<<<blocks((long long)NA * 64), TB>>>(out + (size_t)NP * 64, b2 + 128,
                                                 (const float*)nullptr, NA, 64, 0);
}

// round 2
// speedup vs baseline: 1.0548x; 1.0548x over previous
#include <cuda_runtime.h>
#include <cuda_bf16.h>
#include <cstdint>

#define NP 100000
#define NA 50000
#define EPP 1600000
#define EAP 800000
#define EPA 800000

// ---------------- scratch ----------------------------------------------------
__device__ __align__(16) float g_hs[NP * 128];     // transformed src features
__device__ __align__(16) float g_tmp[NP * 128];    // unnormalized numerator accum
__device__ __align__(16) float g_es[NP * 4];       // per-src attn logits
__device__ __align__(16) float g_ed[NP * 4];       // per-dst attn logits
__device__ __align__(16) float g_den[NP * 4];      // segment expsum
__device__ __align__(16) float g_accp[NP * 128];   // layer1 paper result
__device__ __align__(16) float g_acca[NA * 128];   // layer1 author result
__device__ __align__(16) float g_vd1[3 * 128 * 4]; // Wdst1 . adst1 folded
__device__ __align__(16) float g_vd2[3 * 128 * 4];

// ---------------- helpers ----------------------------------------------------
__device__ __forceinline__ float lrelu(float x) { return x > 0.f ? x : 0.2f * x; }

__device__ __forceinline__ void redAdd4(float* p, float4 v) {
    asm volatile("red.global.add.v4.f32 [%0], {%1,%2,%3,%4};"
                 :: "l"(p), "f"(v.x), "f"(v.y), "f"(v.z), "f"(v.w) : "memory");
}

// ---------------- generic fill -----------------------------------------------
__global__ void fill_kernel(float* __restrict__ p, float v, int n) {
    int i = blockIdx.x * blockDim.x + threadIdx.x;
    if (i < n) p[i] = v;
}

// ---------------- SGEMM: C[M,N] = A[M,128] @ B[128,N]  (N multiple of 64) -----
__global__ void sgemm(const float* __restrict__ A, const float* __restrict__ B,
                      float* __restrict__ C, int M, int N) {
    const int K = 128;
    __shared__ float As[16][68];   // 68*4=272B rows, 16B aligned
    __shared__ float Bs[16][64];
    int tid = threadIdx.x;
    int m0 = blockIdx.y * 64, n0 = blockIdx.x * 64;
    int aRow = tid >> 2, aCol = (tid & 3) << 2;
    int bRow = tid >> 4, bCol = (tid & 15) << 2;
    int tx = tid & 15, ty = tid >> 4;
    float acc[4][4] = {};
    for (int k0 = 0; k0 < K; k0 += 16) {
        float4 av = make_float4(0.f, 0.f, 0.f, 0.f);
        if (m0 + aRow < M)
            av = *(const float4*)(A + (size_t)(m0 + aRow) * K + k0 + aCol);
        As[aCol + 0][aRow] = av.x;
        As[aCol + 1][aRow] = av.y;
        As[aCol + 2][aRow] = av.z;
        As[aCol + 3][aRow] = av.w;
        *(float4*)&Bs[bRow][bCol] =
            *(const float4*)(B + (size_t)(k0 + bRow) * N + n0 + bCol);
        __syncthreads();
#pragma unroll
        for (int k = 0; k < 16; k++) {
            float4 a4 = *(const float4*)&As[k][ty * 4];   // LDS.128
            float4 b4 = *(const float4*)&Bs[k][tx * 4];   // LDS.128
            float a[4] = {a4.x, a4.y, a4.z, a4.w};
            float b[4] = {b4.x, b4.y, b4.z, b4.w};
#pragma unroll
            for (int i = 0; i < 4; i++)
#pragma unroll
                for (int j = 0; j < 4; j++) acc[i][j] += a[i] * b[j];
        }
        __syncthreads();
    }
#pragma unroll
    for (int i = 0; i < 4; i++) {
        int m = m0 + ty * 4 + i;
        if (m < M) {
            float4 o = make_float4(acc[i][0], acc[i][1], acc[i][2], acc[i][3]);
            *(float4*)(C + (size_t)m * N + n0 + tx * 4) = o;
        }
    }
}

// ---------------- vd[r][f][h] = sum_c Wd[r][f][h*C+c] * ad[r][h][c] -----------
__global__ void compute_vd(const float* __restrict__ Wd, const float* __restrict__ ad,
                           float* __restrict__ vd, int D, int C) {
    int i = blockIdx.x * blockDim.x + threadIdx.x;
    if (i >= 3 * 128 * 4) return;
    int h = i & 3;
    int f = (i >> 2) & 127;
    int r = i >> 9;
    const float* W = Wd + (size_t)r * 128 * D + (size_t)f * D + h * C;
    const float* a = ad + r * 4 * C + h * C;
    float s = 0.f;
    for (int c = 0; c < C; c++) s += W[c] * a[c];
    vd[r * 512 + f * 4 + h] = s;
}

// ---------------- es[n,h] = sum_c hs[n,h*C+c] * a[h*C+c] ----------------------
__global__ void es_reduce(const float* __restrict__ hs, const float* __restrict__ a,
                          float* __restrict__ es, int N, int D, int C) {
    int gid = blockIdx.x * blockDim.x + threadIdx.x;
    int G = D >> 2;
    int g = gid / G;
    int l = gid % G;
    bool valid = g < N;
    if (!valid) g = 0;
    float4 h4 = ((const float4*)hs)[(size_t)g * G + l];
    float4 a4 = ((const float4*)a)[l];
    float p = h4.x * a4.x + h4.y * a4.y + h4.z * a4.z + h4.w * a4.w;
    int red = C >> 2;
    for (int off = red >> 1; off; off >>= 1)
        p += __shfl_down_sync(0xffffffffu, p, off, red);
    if (valid && (l % red) == 0) es[g * 4 + l / red] = p;
}

// ---------------- ed[n,:] = x[n,:] @ vd[128,4]  (warp per node) ---------------
__global__ void ed_matvec(const float* __restrict__ x, const float* __restrict__ vd,
                          float* __restrict__ ed, int N) {
    int warp = (blockIdx.x * blockDim.x + threadIdx.x) >> 5;
    int lane = threadIdx.x & 31;
    if (warp >= N) return;
    float4 x4 = ((const float4*)x)[(size_t)warp * 32 + lane];
    const float4* v4 = (const float4*)vd;
    float4 a0 = v4[4 * lane + 0], a1 = v4[4 * lane + 1];
    float4 a2 = v4[4 * lane + 2], a3 = v4[4 * lane + 3];
    float4 acc;
    acc.x = x4.x * a0.x + x4.y * a1.x + x4.z * a2.x + x4.w * a3.x;
    acc.y = x4.x * a0.y + x4.y * a1.y + x4.z * a2.y + x4.w * a3.y;
    acc.z = x4.x * a0.z + x4.y * a1.z + x4.z * a2.z + x4.w * a3.z;
    acc.w = x4.x * a0.w + x4.y * a1.w + x4.z * a2.w + x4.w * a3.w;
    for (int off = 16; off; off >>= 1) {
        acc.x += __shfl_down_sync(0xffffffffu, acc.x, off);
        acc.y += __shfl_down_sync(0xffffffffu, acc.y, off);
        acc.z += __shfl_down_sync(0xffffffffu, acc.z, off);
        acc.w += __shfl_down_sync(0xffffffffu, acc.w, off);
    }
    if (lane == 0) ((float4*)ed)[warp] = acc;
}

// ---------------- FUSED edge pass: tmp[dst] += ee*hs[src], den[dst] += ee -----
template <int D, int C>
__global__ void edge_fused(const int* __restrict__ src, const int* __restrict__ dst,
                           const float* __restrict__ es, const float* __restrict__ ed,
                           const float* __restrict__ hs, float* __restrict__ tmp,
                           float* __restrict__ den, int E) {
    constexpr int G = D / 4;        // lanes per edge (32 or 16)
    constexpr int LPH = C / 4;      // lanes per head (8 or 4)
    int gid = blockIdx.x * blockDim.x + threadIdx.x;
    int e = gid / G;
    bool valid = e < E;
    if (!valid) e = 0;
    int lane = threadIdx.x & 31;
    int lg = lane & (G - 1);
    int base = lane - lg;
    int s = src[e], d = dst[e];
    float ee = 0.f;
    if (lg < 4)
        ee = __expf(lrelu(es[s * 4 + lg] + ed[d * 4 + lg]));
    float e0 = __shfl_sync(0xffffffffu, ee, base + 0);
    float e1 = __shfl_sync(0xffffffffu, ee, base + 1);
    float e2 = __shfl_sync(0xffffffffu, ee, base + 2);
    float e3 = __shfl_sync(0xffffffffu, ee, base + 3);
    if (valid && lg == 0)
        redAdd4(den + (size_t)d * 4, make_float4(e0, e1, e2, e3));
    int h = lg / LPH;
    float a = (h == 0) ? e0 : (h == 1) ? e1 : (h == 2) ? e2 : e3;
    float4 v = ((const float4*)hs)[(size_t)s * G + lg];
    if (valid)
        redAdd4(tmp + (size_t)d * D + lg * 4,
                make_float4(v.x * a, v.y * a, v.z * a, v.w * a));
}

// ---------------- normalize (+accumulate into acc) ----------------------------
template <int C, bool ADD>
__global__ void norm_add(const float* __restrict__ tmp, const float* __restrict__ den,
                         float* __restrict__ acc, int N, int D) {
    int i = blockIdx.x * blockDim.x + threadIdx.x;
    int nv = N * (D / 4);
    if (i >= nv) return;
    int d = i / (D / 4);
    int q = i % (D / 4);
    int h = (q * 4) / C;
    float inv = 1.f / (den[d * 4 + h] + 1e-16f);
    float4 t = ((const float4*)tmp)[i];
    float4 o = make_float4(t.x * inv, t.y * inv, t.z * inv, t.w * inv);
    if (ADD) {
        float4 a = ((const float4*)acc)[i];
        o.x += a.x; o.y += a.y; o.z += a.z; o.w += a.w;
    }
    ((float4*)acc)[i] = o;
}

// ---------------- bias (+ optional relu), in place ----------------------------
__global__ void bias_act(float* __restrict__ acc, const float* __restrict__ b0,
                         const float* __restrict__ b1, int n, int D, int relu) {
    int i = blockIdx.x * blockDim.x + threadIdx.x;
    if (i >= n * D) return;
    int j = i % D;
    float v = acc[i] + b0[j] + (b1 ? b1[j] : 0.f);
    acc[i] = relu ? fmaxf(v, 0.f) : v;
}

// =============================================================================
extern "C" void kernel_launch(void* const* d_in, const int* in_sizes, int n_in,
                              void* d_out, int out_size) {
    const float* x_p = (const float*)d_in[0];
    const float* x_a = (const float*)d_in[1];
    const int* src_pp = (const int*)d_in[2];
    const int* dst_pp = (const int*)d_in[3];
    const int* src_ap = (const int*)d_in[4];
    const int* dst_ap = (const int*)d_in[5];
    const int* src_pa = (const int*)d_in[6];
    const int* dst_pa = (const int*)d_in[7];
    const float* Wsrc1 = (const float*)d_in[8];
    const float* Wdst1 = (const float*)d_in[9];
    const float* asrc1 = (const float*)d_in[10];
    const float* adst1 = (const float*)d_in[11];
    const float* b1 = (const float*)d_in[12];
    const float* Wsrc2 = (const float*)d_in[13];
    const float* Wdst2 = (const float*)d_in[14];
    const float* asrc2 = (const float*)d_in[15];
    const float* adst2 = (const float*)d_in[16];
    const float* b2 = (const float*)d_in[17];
    float* out = (float*)d_out;

    void* p;
    cudaGetSymbolAddress(&p, g_hs);   float* hs   = (float*)p;
    cudaGetSymbolAddress(&p, g_tmp);  float* tmp  = (float*)p;
    cudaGetSymbolAddress(&p, g_es);   float* es   = (float*)p;
    cudaGetSymbolAddress(&p, g_ed);   float* ed   = (float*)p;
    cudaGetSymbolAddress(&p, g_den);  float* den  = (float*)p;
    cudaGetSymbolAddress(&p, g_accp); float* accp = (float*)p;
    cudaGetSymbolAddress(&p, g_acca); float* acca = (float*)p;
    cudaGetSymbolAddress(&p, g_vd1);  float* vd1  = (float*)p;
    cudaGetSymbolAddress(&p, g_vd2);  float* vd2  = (float*)p;

    const int TB = 256;
    auto blocks = [](long long n) { return (int)((n + 255) / 256); };

    compute_vd<<<blocks(3 * 128 * 4), TB>>>(Wdst1, adst1, vd1, 128, 32);
    compute_vd<<<blocks(3 * 128 * 4), TB>>>(Wdst2, adst2, vd2, 64, 16);

    // one conv: sgemm -> es/ed -> fused edge pass -> normalize(+add) into acc
    auto conv = [&](const float* xs, int Ns, const float* xd, int Nd,
                    const int* src, const int* dst, int E,
                    const float* Ws, const float* a_s, const float* vd,
                    float* acc, int D, int C, bool add) {
        fill_kernel<<<blocks((long long)Nd * D), TB>>>(tmp, 0.f, Nd * D);
        fill_kernel<<<blocks(Nd * 4), TB>>>(den, 0.f, Nd * 4);
        dim3 grid(D / 64, (Ns + 63) / 64);
        sgemm<<<grid, 256>>>(xs, Ws, hs, Ns, D);
        int G = D / 4;
        es_reduce<<<blocks((long long)Ns * G), TB>>>(hs, a_s, es, Ns, D, C);
        ed_matvec<<<blocks((long long)Nd * 32), TB>>>(xd, vd, ed, Nd);
        if (D == 128)
            edge_fused<128, 32><<<blocks((long long)E * 32), TB>>>(src, dst, es, ed, hs, tmp, den, E);
        else
            edge_fused<64, 16><<<blocks((long long)E * 16), TB>>>(src, dst, es, ed, hs, tmp, den, E);
        int nv = Nd * (D / 4);
        if (D == 128) {
            if (add) norm_add<32, true><<<blocks(nv), TB>>>(tmp, den, acc, Nd, D);
            else     norm_add<32, false><<<blocks(nv), TB>>>(tmp, den, acc, Nd, D);
        } else {
            if (add) norm_add<16, true><<<blocks(nv), TB>>>(tmp, den, acc, Nd, D);
            else     norm_add<16, false><<<blocks(nv), TB>>>(tmp, den, acc, Nd, D);
        }
    };

    // ---------------- layer 1 (D=128, C=32) ----------------
    conv(x_p, NP, x_p, NP, src_pp, dst_pp, EPP,
         Wsrc1 + 0 * 128 * 128, asrc1 + 0 * 128, vd1 + 0 * 512, accp, 128, 32, false);
    conv(x_a, NA, x_p, NP, src_ap, dst_ap, EAP,
         Wsrc1 + 1 * 128 * 128, asrc1 + 1 * 128, vd1 + 1 * 512, accp, 128, 32, true);
    conv(x_p, NP, x_a, NA, src_pa, dst_pa, EPA,
         Wsrc1 + 2 * 128 * 128, asrc1 + 2 * 128, vd1 + 2 * 512, acca, 128, 32, false);

    bias_act<<<blocks((long long)NP * 128), TB>>>(accp, b1 + 0, b1 + 128, NP, 128, 1);
    bias_act<<<blocks((long long)NA * 128), TB>>>(acca, b1 + 256, (const float*)nullptr, NA, 128, 1);

    // ---------------- layer 2 (D=64, C=16) -> d_out ----------------
    conv(accp, NP, accp, NP, src_pp, dst_pp, EPP,
         Wsrc2 + 0 * 128 * 64, asrc2 + 0 * 64, vd2 + 0 * 512, out, 64, 16, false);
    conv(acca, NA, accp, NP, src_ap, dst_ap, EAP,
         Wsrc2 + 1 * 128 * 64, asrc2 + 1 * 64, vd2 + 1 * 512, out, 64, 16, true);
    conv(accp, NP, acca, NA, src_pa, dst_pa, EPA,
         Wsrc2 + 2 * 128 * 64, asrc2 + 2 * 64, vd2 + 2 * 512, out + (size_t)NP * 64, 64, 16, false);

    bias_act<<<blocks((long long)NP * 64), TB>>>(out, b2 + 0, b2 + 64, NP, 64, 0);
    bias_act<<<blocks((long long)NA * 64), TB>>>(out + (size_t)NP * 64, b2 + 128,
                                                 (const float*)nullptr, NA, 64, 0);
}

// round 3
// speedup vs baseline: 1.1482x; 1.0885x over previous
#include <cuda_runtime.h>
#include <cuda_bf16.h>
#include <cstdint>

#define NP 100000
#define NA 50000
#define EPP 1600000
#define EAP 800000
#define EPA 800000

// ---------------- scratch ----------------------------------------------------
__device__ __align__(16) float g_hs[NP * 128];
__device__ __align__(16) float g_tmp[NP * 128];
__device__ __align__(16) float g_es[NP * 4];
__device__ __align__(16) float g_ed[NP * 4];
__device__ __align__(16) float g_den[NP * 4];
__device__ __align__(16) float g_accp[NP * 128];
__device__ __align__(16) float g_acca[NA * 128];
__device__ __align__(16) float g_vd1[3 * 128 * 4];
__device__ __align__(16) float g_vd2[3 * 128 * 4];

// ---------------- helpers ----------------------------------------------------
__device__ __forceinline__ float lrelu(float x) { return x > 0.f ? x : 0.2f * x; }

__device__ __forceinline__ void redAdd4(float* p, float4 v) {
    asm volatile("red.global.add.v4.f32 [%0], {%1,%2,%3,%4};"
                 :: "l"(p), "f"(v.x), "f"(v.y), "f"(v.z), "f"(v.w) : "memory");
}

__global__ void fill_kernel(float* __restrict__ p, float v, int n) {
    int i = blockIdx.x * blockDim.x + threadIdx.x;
    if (i < n) p[i] = v;
}

// ---------------- SGEMM: C[M,N] = A[M,128] @ B[128,N] ------------------------
// 128x64 tile, 256 threads, 8x4 per thread, double-buffered smem, 1 sync/chunk.
#define BM 128
#define BN 64
#define BK 16
__global__ void __launch_bounds__(256)
sgemm(const float* __restrict__ A, const float* __restrict__ B,
      float* __restrict__ C, int M, int N) {
    const int K = 128;
    __shared__ float As[2][BK][BM + 4];
    __shared__ float Bs[2][BK][BN];
    int tid = threadIdx.x;
    int m0 = blockIdx.y * BM, n0 = blockIdx.x * BN;

    int aRow = tid >> 1;            // 0..127
    int aC4 = (tid & 1) * 2;        // float4 group 0/2
    int bK = tid >> 4;              // 0..15
    int bC4 = tid & 15;             // 0..15

    int ty = tid >> 4;              // 0..15 -> 8 rows each
    int tx = tid & 15;              // 0..15 -> 4 cols each

    float acc[8][4] = {};
    float4 ra0, ra1, rb;

    auto loadg = [&](int k0) {
        int m = m0 + aRow;
        if (m < M) {
            ra0 = *(const float4*)(A + (size_t)m * K + k0 + aC4 * 4);
            ra1 = *(const float4*)(A + (size_t)m * K + k0 + aC4 * 4 + 4);
        } else {
            ra0 = make_float4(0.f, 0.f, 0.f, 0.f);
            ra1 = ra0;
        }
        rb = *(const float4*)(B + (size_t)(k0 + bK) * N + n0 + bC4 * 4);
    };
    auto stores = [&](int buf) {
        As[buf][aC4 * 4 + 0][aRow] = ra0.x;
        As[buf][aC4 * 4 + 1][aRow] = ra0.y;
        As[buf][aC4 * 4 + 2][aRow] = ra0.z;
        As[buf][aC4 * 4 + 3][aRow] = ra0.w;
        As[buf][aC4 * 4 + 4][aRow] = ra1.x;
        As[buf][aC4 * 4 + 5][aRow] = ra1.y;
        As[buf][aC4 * 4 + 6][aRow] = ra1.z;
        As[buf][aC4 * 4 + 7][aRow] = ra1.w;
        *(float4*)&Bs[buf][bK][bC4 * 4] = rb;
    };

    loadg(0);
    stores(0);
    __syncthreads();

    const int NCH = K / BK;   // 8
#pragma unroll
    for (int c = 0; c < NCH; c++) {
        if (c + 1 < NCH) loadg((c + 1) * BK);
        int buf = c & 1;
#pragma unroll
        for (int k = 0; k < BK; k++) {
            float4 a0 = *(const float4*)&As[buf][k][ty * 8];
            float4 a1 = *(const float4*)&As[buf][k][ty * 8 + 4];
            float4 b = *(const float4*)&Bs[buf][k][tx * 4];
            float av[8] = {a0.x, a0.y, a0.z, a0.w, a1.x, a1.y, a1.z, a1.w};
            float bv[4] = {b.x, b.y, b.z, b.w};
#pragma unroll
            for (int i = 0; i < 8; i++)
#pragma unroll
                for (int j = 0; j < 4; j++) acc[i][j] += av[i] * bv[j];
        }
        if (c + 1 < NCH) stores((c + 1) & 1);
        __syncthreads();
    }

#pragma unroll
    for (int i = 0; i < 8; i++) {
        int m = m0 + ty * 8 + i;
        if (m < M) {
            float4 o = make_float4(acc[i][0], acc[i][1], acc[i][2], acc[i][3]);
            *(float4*)(C + (size_t)m * N + n0 + tx * 4) = o;
        }
    }
}

// ---------------- vd folding (both layers, one launch) ------------------------
__global__ void compute_vd(const float* __restrict__ Wd1, const float* __restrict__ ad1,
                           const float* __restrict__ Wd2, const float* __restrict__ ad2,
                           float* __restrict__ vd1, float* __restrict__ vd2) {
    int i = blockIdx.x * blockDim.x + threadIdx.x;
    if (i >= 2 * 3 * 128 * 4) return;
    int layer = i >= 3 * 128 * 4;
    int ii = i - layer * 3 * 128 * 4;
    int h = ii & 3;
    int f = (ii >> 2) & 127;
    int r = ii >> 9;
    int D = layer ? 64 : 128;
    int C = D / 4;
    const float* W = (layer ? Wd2 : Wd1) + (size_t)r * 128 * D + (size_t)f * D + h * C;
    const float* a = (layer ? ad2 : ad1) + r * 4 * C + h * C;
    float s = 0.f;
    for (int c = 0; c < C; c++) s += W[c] * a[c];
    (layer ? vd2 : vd1)[r * 512 + f * 4 + h] = s;
}

// ---------------- es[n,h] = sum_c hs[n,h*C+c] * a[h*C+c] ----------------------
__global__ void es_reduce(const float* __restrict__ hs, const float* __restrict__ a,
                          float* __restrict__ es, int N, int D, int C) {
    int gid = blockIdx.x * blockDim.x + threadIdx.x;
    int G = D >> 2;
    int g = gid / G;
    int l = gid % G;
    bool valid = g < N;
    if (!valid) g = 0;
    float4 h4 = ((const float4*)hs)[(size_t)g * G + l];
    float4 a4 = ((const float4*)a)[l];
    float p = h4.x * a4.x + h4.y * a4.y + h4.z * a4.z + h4.w * a4.w;
    int red = C >> 2;
    for (int off = red >> 1; off; off >>= 1)
        p += __shfl_down_sync(0xffffffffu, p, off, red);
    if (valid && (l % red) == 0) es[g * 4 + l / red] = p;
}

// ---------------- ed[n,:] = x[n,:] @ vd[128,4]  (warp per node) ---------------
__global__ void ed_matvec(const float* __restrict__ x, const float* __restrict__ vd,
                          float* __restrict__ ed, int N) {
    int warp = (blockIdx.x * blockDim.x + threadIdx.x) >> 5;
    int lane = threadIdx.x & 31;
    if (warp >= N) return;
    float4 x4 = ((const float4*)x)[(size_t)warp * 32 + lane];
    const float4* v4 = (const float4*)vd;
    float4 a0 = v4[4 * lane + 0], a1 = v4[4 * lane + 1];
    float4 a2 = v4[4 * lane + 2], a3 = v4[4 * lane + 3];
    float4 acc;
    acc.x = x4.x * a0.x + x4.y * a1.x + x4.z * a2.x + x4.w * a3.x;
    acc.y = x4.x * a0.y + x4.y * a1.y + x4.z * a2.y + x4.w * a3.y;
    acc.z = x4.x * a0.z + x4.y * a1.z + x4.z * a2.z + x4.w * a3.z;
    acc.w = x4.x * a0.w + x4.y * a1.w + x4.z * a2.w + x4.w * a3.w;
    for (int off = 16; off; off >>= 1) {
        acc.x += __shfl_down_sync(0xffffffffu, acc.x, off);
        acc.y += __shfl_down_sync(0xffffffffu, acc.y, off);
        acc.z += __shfl_down_sync(0xffffffffu, acc.z, off);
        acc.w += __shfl_down_sync(0xffffffffu, acc.w, off);
    }
    if (lane == 0) ((float4*)ed)[warp] = acc;
}

// ---------------- FUSED edge pass: tmp[dst] += ee*hs[src], den[dst] += ee -----
template <int D, int C>
__global__ void edge_fused(const int* __restrict__ src, const int* __restrict__ dst,
                           const float* __restrict__ es, const float* __restrict__ ed,
                           const float* __restrict__ hs, float* __restrict__ tmp,
                           float* __restrict__ den, int E) {
    constexpr int G = D / 4;
    constexpr int LPH = C / 4;
    int gid = blockIdx.x * blockDim.x + threadIdx.x;
    int e = gid / G;
    bool valid = e < E;
    if (!valid) e = 0;
    int lane = threadIdx.x & 31;
    int lg = lane & (G - 1);
    int base = lane - lg;
    int s = src[e], d = dst[e];
    float ee = 0.f;
    if (lg < 4)
        ee = __expf(lrelu(es[s * 4 + lg] + ed[d * 4 + lg]));
    float e0 = __shfl_sync(0xffffffffu, ee, base + 0);
    float e1 = __shfl_sync(0xffffffffu, ee, base + 1);
    float e2 = __shfl_sync(0xffffffffu, ee, base + 2);
    float e3 = __shfl_sync(0xffffffffu, ee, base + 3);
    if (valid && lg == 0)
        redAdd4(den + (size_t)d * 4, make_float4(e0, e1, e2, e3));
    int h = lg / LPH;
    float a = (h == 0) ? e0 : (h == 1) ? e1 : (h == 2) ? e2 : e3;
    float4 v = ((const float4*)hs)[(size_t)s * G + lg];
    if (valid)
        redAdd4(tmp + (size_t)d * D + lg * 4,
                make_float4(v.x * a, v.y * a, v.z * a, v.w * a));
}

// ---------------- normalize + optional add + optional bias/relu ---------------
template <int C>
__global__ void norm_add(const float* __restrict__ tmp, const float* __restrict__ den,
                         float* __restrict__ acc, int N, int D, int add,
                         const float* __restrict__ bias0, const float* __restrict__ bias1,
                         int relu) {
    int i = blockIdx.x * blockDim.x + threadIdx.x;
    int nv = N * (D / 4);
    if (i >= nv) return;
    int d = i / (D / 4);
    int q = i % (D / 4);
    int h = (q * 4) / C;
    float inv = 1.f / (den[d * 4 + h] + 1e-16f);
    float4 t = ((const float4*)tmp)[i];
    float4 o = make_float4(t.x * inv, t.y * inv, t.z * inv, t.w * inv);
    if (add) {
        float4 a = ((const float4*)acc)[i];
        o.x += a.x; o.y += a.y; o.z += a.z; o.w += a.w;
    }
    if (bias0) {
        float4 b = *(const float4*)(bias0 + q * 4);
        o.x += b.x; o.y += b.y; o.z += b.z; o.w += b.w;
    }
    if (bias1) {
        float4 b = *(const float4*)(bias1 + q * 4);
        o.x += b.x; o.y += b.y; o.z += b.z; o.w += b.w;
    }
    if (relu) {
        o.x = fmaxf(o.x, 0.f); o.y = fmaxf(o.y, 0.f);
        o.z = fmaxf(o.z, 0.f); o.w = fmaxf(o.w, 0.f);
    }
    ((float4*)acc)[i] = o;
}

// =============================================================================
extern "C" void kernel_launch(void* const* d_in, const int* in_sizes, int n_in,
                              void* d_out, int out_size) {
    const float* x_p = (const float*)d_in[0];
    const float* x_a = (const float*)d_in[1];
    const int* src_pp = (const int*)d_in[2];
    const int* dst_pp = (const int*)d_in[3];
    const int* src_ap = (const int*)d_in[4];
    const int* dst_ap = (const int*)d_in[5];
    const int* src_pa = (const int*)d_in[6];
    const int* dst_pa = (const int*)d_in[7];
    const float* Wsrc1 = (const float*)d_in[8];
    const float* Wdst1 = (const float*)d_in[9];
    const float* asrc1 = (const float*)d_in[10];
    const float* adst1 = (const float*)d_in[11];
    const float* b1 = (const float*)d_in[12];
    const float* Wsrc2 = (const float*)d_in[13];
    const float* Wdst2 = (const float*)d_in[14];
    const float* asrc2 = (const float*)d_in[15];
    const float* adst2 = (const float*)d_in[16];
    const float* b2 = (const float*)d_in[17];
    float* out = (float*)d_out;

    void* p;
    cudaGetSymbolAddress(&p, g_hs);   float* hs   = (float*)p;
    cudaGetSymbolAddress(&p, g_tmp);  float* tmp  = (float*)p;
    cudaGetSymbolAddress(&p, g_es);   float* es   = (float*)p;
    cudaGetSymbolAddress(&p, g_ed);   float* ed   = (float*)p;
    cudaGetSymbolAddress(&p, g_den);  float* den  = (float*)p;
    cudaGetSymbolAddress(&p, g_accp); float* accp = (float*)p;
    cudaGetSymbolAddress(&p, g_acca); float* acca = (float*)p;
    cudaGetSymbolAddress(&p, g_vd1);  float* vd1  = (float*)p;
    cudaGetSymbolAddress(&p, g_vd2);  float* vd2  = (float*)p;

    const int TB = 256;
    auto blocks = [](long long n) { return (int)((n + 255) / 256); };

    compute_vd<<<blocks(2 * 3 * 128 * 4), TB>>>(Wdst1, adst1, Wdst2, adst2, vd1, vd2);

    auto conv = [&](const float* xs, int Ns, const float* xd, int Nd,
                    const int* src, const int* dst, int E,
                    const float* Ws, const float* a_s, const float* vd,
                    float* acc, int D, int C, bool add,
                    const float* bias0, const float* bias1, int relu) {
        dim3 grid(D / 64, (Ns + BM - 1) / BM);
        sgemm<<<grid, 256>>>(xs, Ws, hs, Ns, D);
        int G = D / 4;
        es_reduce<<<blocks((long long)Ns * G), TB>>>(hs, a_s, es, Ns, D, C);
        ed_matvec<<<blocks((long long)Nd * 32), TB>>>(xd, vd, ed, Nd);
        fill_kernel<<<blocks((long long)Nd * D), TB>>>(tmp, 0.f, Nd * D);
        fill_kernel<<<blocks(Nd * 4), TB>>>(den, 0.f, Nd * 4);
        if (D == 128)
            edge_fused<128, 32><<<blocks((long long)E * 32), TB>>>(src, dst, es, ed, hs, tmp, den, E);
        else
            edge_fused<64, 16><<<blocks((long long)E * 16), TB>>>(src, dst, es, ed, hs, tmp, den, E);
        int nv = Nd * (D / 4);
        if (D == 128)
            norm_add<32><<<blocks(nv), TB>>>(tmp, den, acc, Nd, D, add, bias0, bias1, relu);
        else
            norm_add<16><<<blocks(nv), TB>>>(tmp, den, acc, Nd, D, add, bias0, bias1, relu);
    };

    // ---------------- layer 1 (D=128, C=32) ----------------
    conv(x_p, NP, x_p, NP, src_pp, dst_pp, EPP,
         Wsrc1 + 0 * 128 * 128, asrc1 + 0 * 128, vd1 + 0 * 512, accp, 128, 32, false,
         nullptr, nullptr, 0);
    conv(x_a, NA, x_p, NP, src_ap, dst_ap, EAP,
         Wsrc1 + 1 * 128 * 128, asrc1 + 1 * 128, vd1 + 1 * 512, accp, 128, 32, true,
         b1 + 0, b1 + 128, 1);
    conv(x_p, NP, x_a, NA, src_pa, dst_pa, EPA,
         Wsrc1 + 2 * 128 * 128, asrc1 + 2 * 128, vd1 + 2 * 512, acca, 128, 32, false,
         b1 + 256, nullptr, 1);

    // ---------------- layer 2 (D=64, C=16) -> d_out ----------------
    conv(accp, NP, accp, NP, src_pp, dst_pp, EPP,
         Wsrc2 + 0 * 128 * 64, asrc2 + 0 * 64, vd2 + 0 * 512, out, 64, 16, false,
         nullptr, nullptr, 0);
    conv(acca, NA, accp, NP, src_ap, dst_ap, EAP,
         Wsrc2 + 1 * 128 * 64, asrc2 + 1 * 64, vd2 + 1 * 512, out, 64, 16, true,
         b2 + 0, b2 + 64, 0);
    conv(accp, NP, acca, NA, src_pa, dst_pa, EPA,
         Wsrc2 + 2 * 128 * 64, asrc2 + 2 * 64, vd2 + 2 * 512, out + (size_t)NP * 64, 64, 16, false,
         b2 + 128, nullptr, 0);
}